// round 1
// baseline (speedup 1.0000x reference)
#include <cuda_runtime.h>
#include <float.h>

#define B_       16
#define C_       80
#define N_       25200
#define N0_      19200
#define N1_      4800
#define N2_      1200
#define K_       25
#define NEG      (-1e30f)
#define SCORE_T  0.55f
#define IOU_T    0.5f
#define MAXC     4096
#define NTH      512

// Phase-1 scratch: per (b,c,k) kept box + masked score.
__device__ float g_kb[B_ * C_ * K_ * 4];
__device__ float g_ks[B_ * C_ * K_];

// ---------------------------------------------------------------------------
// Kernel 1: per-(batch,class) greedy NMS. grid = B_*C_, block = NTH.
// Dynamic smem: float4 box[MAXC] + float score[MAXC] = 81920 B.
// ---------------------------------------------------------------------------
__global__ __launch_bounds__(NTH) void nms_kernel(
    const float* __restrict__ bbox0, const float* __restrict__ conf0, const float* __restrict__ cls0,
    const float* __restrict__ bbox1, const float* __restrict__ conf1, const float* __restrict__ cls1,
    const float* __restrict__ bbox2, const float* __restrict__ conf2, const float* __restrict__ cls2)
{
    extern __shared__ float smem[];
    float4* s_box   = (float4*)smem;            // MAXC float4
    float*  s_score = (float*)(s_box + MAXC);   // MAXC float

    __shared__ int    s_cnt;
    __shared__ int    s_wcnt[NTH / 32];
    __shared__ float  r_s[NTH];
    __shared__ int    r_i[NTH];
    __shared__ float4 sh_bbox;
    __shared__ float  sh_bs;
    __shared__ int    sh_bi;

    const int tid  = threadIdx.x;
    const int b    = blockIdx.x / C_;
    const int c    = blockIdx.x - b * C_;
    const int warp = tid >> 5;
    const int lane = tid & 31;

    if (tid == 0) s_cnt = 0;
    __syncthreads();

    // ---- Pass 1: order-preserving compaction of candidates (score > SCORE_T)
    for (int base = 0; base < N_; base += NTH) {
        int   n    = base + tid;
        bool  pred = false;
        float sc   = 0.f;
        float4 bx  = make_float4(0.f, 0.f, 0.f, 0.f);
        if (n < N_) {
            const float *bb, *cf, *cl;
            int loc;
            if (n < N0_)              { bb = bbox0; cf = conf0; cl = cls0; loc = b * N0_ + n; }
            else if (n < N0_ + N1_)   { bb = bbox1; cf = conf1; cl = cls1; loc = b * N1_ + (n - N0_); }
            else                      { bb = bbox2; cf = conf2; cl = cls2; loc = b * N2_ + (n - N0_ - N1_); }
            float cfv = cf[loc];
            float pv  = cl[loc * C_ + c];
            sc   = cfv * pv;                    // same single f32 mul as reference
            pred = sc > SCORE_T;
            if (pred) {
                float4 t = ((const float4*)bb)[loc];
                bx.x = fmaxf(t.x, 0.f); bx.y = fmaxf(t.y, 0.f);
                bx.z = fmaxf(t.z, 0.f); bx.w = fmaxf(t.w, 0.f);
            }
        }
        unsigned m = __ballot_sync(0xffffffffu, pred);
        if (lane == 0) s_wcnt[warp] = __popc(m);
        __syncthreads();
        int off = s_cnt;
        for (int w = 0; w < warp; w++) off += s_wcnt[w];
        int pos = off + __popc(m & ((1u << lane) - 1u));
        if (pred && pos < MAXC) { s_score[pos] = sc; s_box[pos] = bx; }
        __syncthreads();
        if (tid == 0) {
            int t = 0;
            #pragma unroll
            for (int w = 0; w < NTH / 32; w++) t += s_wcnt[w];
            s_cnt += t;
        }
        __syncthreads();
    }
    const int cnt = min(s_cnt, MAXC);
    const int out_base = blockIdx.x * K_;

    // ---- Pass 2: greedy NMS, K_ picks
    int k = 0;
    for (; k < K_; k++) {
        // block argmax, first-index tie-break (matches jnp.argmax)
        float best = NEG;
        int   bi   = -1;
        for (int i = tid; i < cnt; i += NTH) {
            float s = s_score[i];
            if (s > best) { best = s; bi = i; }   // strided ascending -> keeps first tie
        }
        r_s[tid] = best; r_i[tid] = bi;
        __syncthreads();
        for (int st = NTH / 2; st > 0; st >>= 1) {
            if (tid < st) {
                float s2 = r_s[tid + st]; int i2 = r_i[tid + st];
                if (s2 > r_s[tid] ||
                    (s2 == r_s[tid] && (unsigned)i2 < (unsigned)r_i[tid])) {
                    r_s[tid] = s2; r_i[tid] = i2;
                }
            }
            __syncthreads();
        }
        if (tid == 0) {
            sh_bs = r_s[0];
            sh_bi = r_i[0];
            if (r_i[0] >= 0) sh_bbox = s_box[r_i[0]];
        }
        __syncthreads();

        float bs   = sh_bs;
        int   biG  = sh_bi;
        bool  valid = bs > SCORE_T;
        if (!valid) break;                       // all remaining picks are invalid too

        if (tid == 0) {
            g_ks[out_base + k] = bs;             // already "where(kv, ks, NEG)"-masked form
            ((float4*)g_kb)[out_base + k] = sh_bbox;
        }

        // suppress: iou(best, i) > IOU_T, plus the pick itself
        float4 Bx = sh_bbox;
        float by1 = fminf(Bx.x, Bx.z), by2 = fmaxf(Bx.x, Bx.z);
        float bx1 = fminf(Bx.y, Bx.w), bx2 = fmaxf(Bx.y, Bx.w);
        float ba  = (by2 - by1) * (bx2 - bx1);
        for (int i = tid; i < cnt; i += NTH) {
            float s = s_score[i];
            if (s == NEG) continue;
            float4 Q = s_box[i];
            float qy1 = fminf(Q.x, Q.z), qy2 = fmaxf(Q.x, Q.z);
            float qx1 = fminf(Q.y, Q.w), qx2 = fmaxf(Q.y, Q.w);
            float ih = fmaxf(fminf(by2, qy2) - fmaxf(by1, qy1), 0.f);
            float iw = fmaxf(fminf(bx2, qx2) - fmaxf(bx1, qx1), 0.f);
            float inter = ih * iw;
            float qa = (qy2 - qy1) * (qx2 - qx1);
            float un = ba + qa - inter;
            float iou = (un > 0.f) ? __fdiv_rn(inter, un) : 0.f;  // IEEE div, fast-math-proof
            if (iou > IOU_T || i == biG) s_score[i] = NEG;
        }
        __syncthreads();
    }

    // fill unused slots (invalid picks)
    for (int kk = k + tid; kk < K_; kk += NTH) {
        g_ks[out_base + kk] = NEG;
        ((float4*)g_kb)[out_base + kk] = make_float4(0.f, 0.f, 0.f, 0.f);
    }
}

// ---------------------------------------------------------------------------
// Kernel 2: per-batch cross-class top-K_. grid = B_, block = 256.
// Output layout (all f32): boxes [B,K,4] | scores [B,K] | cls [B,K] | valid [B]
// ---------------------------------------------------------------------------
__global__ __launch_bounds__(256) void topk_kernel(float* __restrict__ out)
{
    __shared__ float s_s[C_ * K_];
    __shared__ float r_s[256];
    __shared__ int   r_i[256];
    __shared__ int   s_vcnt;

    const int b   = blockIdx.x;
    const int tid = threadIdx.x;

    for (int j = tid; j < C_ * K_; j += 256) s_s[j] = g_ks[b * C_ * K_ + j];
    if (tid == 0) s_vcnt = 0;
    __syncthreads();

    const int OB_scores = B_ * K_ * 4;
    const int OB_cls    = OB_scores + B_ * K_;
    const int OB_valid  = OB_cls + B_ * K_;

    for (int k = 0; k < K_; k++) {
        float best = -FLT_MAX;
        int   bi   = -1;
        for (int i = tid; i < C_ * K_; i += 256) {
            float s = s_s[i];
            if (s > best) { best = s; bi = i; }
        }
        r_s[tid] = best; r_i[tid] = bi;
        __syncthreads();
        for (int st = 128; st > 0; st >>= 1) {
            if (tid < st) {
                float s2 = r_s[tid + st]; int i2 = r_i[tid + st];
                if (s2 > r_s[tid] ||
                    (s2 == r_s[tid] && (unsigned)i2 < (unsigned)r_i[tid])) {
                    r_s[tid] = s2; r_i[tid] = i2;
                }
            }
            __syncthreads();
        }
        if (tid == 0) {
            float s   = r_s[0];
            int   idx = r_i[0];
            bool valid = s > SCORE_T;
            if (valid) s_vcnt++;
            float4 bx = make_float4(0.f, 0.f, 0.f, 0.f);
            if (valid) {
                bx = ((float4*)g_kb)[b * C_ * K_ + idx];
                bx.x = fminf(fmaxf(bx.x, 0.f), 1.f);
                bx.y = fminf(fmaxf(bx.y, 0.f), 1.f);
                bx.z = fminf(fmaxf(bx.z, 0.f), 1.f);
                bx.w = fminf(fmaxf(bx.w, 0.f), 1.f);
            }
            int o = b * K_ + k;
            ((float4*)out)[o]    = bx;
            out[OB_scores + o]   = valid ? s : 0.f;
            out[OB_cls + o]      = valid ? (float)(idx / K_) : 0.f;
            s_s[idx] = -FLT_MAX;            // lower than NEG -> never re-picked
        }
        __syncthreads();
    }
    if (tid == 0) out[OB_valid + b] = (float)s_vcnt;
}

// ---------------------------------------------------------------------------
extern "C" void kernel_launch(void* const* d_in, const int* in_sizes, int n_in,
                              void* d_out, int out_size)
{
    const float* bbox0 = (const float*)d_in[0];
    const float* conf0 = (const float*)d_in[1];
    const float* cls0  = (const float*)d_in[2];
    const float* bbox1 = (const float*)d_in[3];
    const float* conf1 = (const float*)d_in[4];
    const float* cls1  = (const float*)d_in[5];
    const float* bbox2 = (const float*)d_in[6];
    const float* conf2 = (const float*)d_in[7];
    const float* cls2  = (const float*)d_in[8];

    const int smem_bytes = MAXC * sizeof(float4) + MAXC * sizeof(float); // 81920
    cudaFuncSetAttribute(nms_kernel, cudaFuncAttributeMaxDynamicSharedMemorySize, smem_bytes);

    nms_kernel<<<B_ * C_, NTH, smem_bytes>>>(bbox0, conf0, cls0,
                                             bbox1, conf1, cls1,
                                             bbox2, conf2, cls2);
    topk_kernel<<<B_, 256>>>((float*)d_out);
}

// round 2
// speedup vs baseline: 1.4387x; 1.4387x over previous
#include <cuda_runtime.h>
#include <float.h>

#define B_       16
#define C_       80
#define N_       25200
#define N0_      19200
#define N1_      4800
#define N2_      1200
#define K_       25
#define NEG      (-1e30f)
#define SCORE_T  0.55f
#define IOU_T    0.5f
#define MAXC     3584
#define NTH      512

// Scratch: transposed scores + per-(b,c,k) kept box/score.
__device__ float g_scores[B_ * C_ * N_];          // 129 MB
__device__ float g_kb[B_ * C_ * K_ * 4];
__device__ float g_ks[B_ * C_ * K_];

// ---------------------------------------------------------------------------
// Kernel 0: score transpose.  score[b][c][n] = conf[b][n] * cls[b][n][c]
// grid = B_ * ceil(N_/32), block = 256.  All reads and writes coalesced.
// ---------------------------------------------------------------------------
__global__ __launch_bounds__(256) void score_kernel(
    const float* __restrict__ conf0, const float* __restrict__ cls0,
    const float* __restrict__ conf1, const float* __restrict__ cls1,
    const float* __restrict__ conf2, const float* __restrict__ cls2)
{
    __shared__ float s_tile[32][81];   // [anchor][class], pad -> conflict-free transpose
    __shared__ float s_conf[32];

    const int NT   = (N_ + 31) / 32;             // 788 tiles
    const int b    = blockIdx.x / NT;
    const int t    = blockIdx.x - b * NT;
    const int n0   = t * 32;
    const int tid  = threadIdx.x;
    const int lane = tid & 31;
    const int va   = min(32, N_ - n0);           // valid anchors in tile

    const float *cf, *cl;
    int loc_base;
    if (n0 < N0_)             { cf = conf0; cl = cls0; loc_base = b * N0_ + n0; }
    else if (n0 < N0_ + N1_)  { cf = conf1; cl = cls1; loc_base = b * N1_ + (n0 - N0_); }
    else                      { cf = conf2; cl = cls2; loc_base = b * N2_ + (n0 - N0_ - N1_); }

    // load cls tile [va x 80] coalesced
    for (int el = tid; el < 32 * C_; el += 256) {
        int a = el / C_, c = el - a * C_;
        if (a < va) s_tile[a][c] = cl[(loc_base + a) * C_ + c];
    }
    if (tid < 32 && tid < va) s_conf[tid] = cf[loc_base + tid];
    __syncthreads();

    // write transposed, coalesced over anchors
    const int cw = tid >> 5;                     // 0..7
    #pragma unroll
    for (int cc = 0; cc < 10; cc++) {
        int c = cw * 10 + cc;                    // 0..79
        if (lane < va)
            g_scores[(b * C_ + c) * N_ + n0 + lane] = s_conf[lane] * s_tile[lane][c];
    }
}

// ---------------------------------------------------------------------------
// block argmax with first-index tie-break (matches jnp.argmax / lax.top_k)
// ---------------------------------------------------------------------------
__device__ __forceinline__ void block_argmax512(
    float s, int i, float* s_rs, int* s_ri, float* sh_bs, int* sh_bi, int tid)
{
    #pragma unroll
    for (int off = 16; off; off >>= 1) {
        float s2 = __shfl_down_sync(0xffffffffu, s, off);
        int   i2 = __shfl_down_sync(0xffffffffu, i, off);
        if (s2 > s || (s2 == s && (unsigned)i2 < (unsigned)i)) { s = s2; i = i2; }
    }
    if ((tid & 31) == 0) { s_rs[tid >> 5] = s; s_ri[tid >> 5] = i; }
    __syncthreads();
    if (tid < 32) {
        s = (tid < NTH / 32) ? s_rs[tid] : NEG;
        i = (tid < NTH / 32) ? s_ri[tid] : -1;
        #pragma unroll
        for (int off = 8; off; off >>= 1) {
            float s2 = __shfl_down_sync(0xffffffffu, s, off);
            int   i2 = __shfl_down_sync(0xffffffffu, i, off);
            if (s2 > s || (s2 == s && (unsigned)i2 < (unsigned)i)) { s = s2; i = i2; }
        }
        if (tid == 0) { *sh_bs = s; *sh_bi = i; }
    }
    __syncthreads();
}

// ---------------------------------------------------------------------------
// Kernel 1: per-(batch,class) greedy NMS. grid = B_*C_, block = NTH.
// Dynamic smem: float4 box[MAXC] + float score[MAXC] = 71680 B -> 3 CTAs/SM.
// ---------------------------------------------------------------------------
__global__ __launch_bounds__(NTH) void nms_kernel(
    const float* __restrict__ bbox0,
    const float* __restrict__ bbox1,
    const float* __restrict__ bbox2)
{
    extern __shared__ float smem[];
    float4* s_box   = (float4*)smem;            // MAXC float4
    float*  s_score = (float*)(s_box + MAXC);   // MAXC float

    __shared__ int   s_wcnt[NTH / 32];
    __shared__ float s_rs[NTH / 32];
    __shared__ int   s_ri[NTH / 32];
    __shared__ float sh_bs;
    __shared__ int   sh_bi;

    const int tid  = threadIdx.x;
    const int b    = blockIdx.x / C_;
    const int c    = blockIdx.x - b * C_;
    const int warp = tid >> 5;
    const int lane = tid & 31;
    const unsigned lmask = (1u << lane) - 1u;

    const float* sc_row = g_scores + (size_t)(b * C_ + c) * N_;

    // ---- Pass 1: order-preserving compaction + fused initial argmax
    int   cnt   = 0;
    float pbest = NEG;
    int   pbi   = -1;

    for (int base = 0; base < N_; base += NTH) {
        int   n    = base + tid;
        bool  pred = false;
        float sc   = 0.f;
        float4 bx;
        if (n < N_) {
            sc   = sc_row[n];                    // coalesced
            pred = sc > SCORE_T;
            if (pred) {
                const float* bb;
                int loc;
                if (n < N0_)            { bb = bbox0; loc = b * N0_ + n; }
                else if (n < N0_ + N1_) { bb = bbox1; loc = b * N1_ + (n - N0_); }
                else                    { bb = bbox2; loc = b * N2_ + (n - N0_ - N1_); }
                float4 tq = ((const float4*)bb)[loc];
                bx.x = fmaxf(tq.x, 0.f); bx.y = fmaxf(tq.y, 0.f);
                bx.z = fmaxf(tq.z, 0.f); bx.w = fmaxf(tq.w, 0.f);
            }
        }
        unsigned m = __ballot_sync(0xffffffffu, pred);
        if (lane == 0) s_wcnt[warp] = __popc(m);
        __syncthreads();
        int off = cnt, tot = 0;
        #pragma unroll
        for (int w = 0; w < NTH / 32; w++) {
            int wc = s_wcnt[w];
            if (w < warp) off += wc;
            tot += wc;
        }
        int pos = off + __popc(m & lmask);
        if (pred && pos < MAXC) {
            s_score[pos] = sc;
            s_box[pos]   = bx;
            if (sc > pbest) { pbest = sc; pbi = pos; }   // ascending pos -> first tie kept
        }
        cnt += tot;
        __syncthreads();
    }
    cnt = min(cnt, MAXC);
    const int out_base = blockIdx.x * K_;

    block_argmax512(pbest, pbi, s_rs, s_ri, &sh_bs, &sh_bi, tid);
    float bs  = sh_bs;
    int   biG = sh_bi;

    // ---- Pass 2: greedy picks, suppression fused with next-argmax
    int k = 0;
    for (; k < K_; k++) {
        if (!(bs > SCORE_T)) break;

        float4 Bx = s_box[biG];                  // smem broadcast
        if (tid == 0) {
            g_ks[out_base + k] = bs;
            ((float4*)g_kb)[out_base + k] = Bx;
        }

        float by1 = fminf(Bx.x, Bx.z), by2 = fmaxf(Bx.x, Bx.z);
        float bx1 = fminf(Bx.y, Bx.w), bx2 = fmaxf(Bx.y, Bx.w);
        float ba  = (by2 - by1) * (bx2 - bx1);

        float nb = NEG; int ni = -1;
        for (int i = tid; i < cnt; i += NTH) {
            float s = s_score[i];
            if (s == NEG) continue;
            if (i == biG) { s_score[i] = NEG; continue; }
            float4 Q = s_box[i];
            float qy1 = fminf(Q.x, Q.z), qy2 = fmaxf(Q.x, Q.z);
            float qx1 = fminf(Q.y, Q.w), qx2 = fmaxf(Q.y, Q.w);
            float ih = fmaxf(fminf(by2, qy2) - fmaxf(by1, qy1), 0.f);
            float iw = fmaxf(fminf(bx2, qx2) - fmaxf(bx1, qx1), 0.f);
            float inter = ih * iw;
            float qa = (qy2 - qy1) * (qx2 - qx1);
            float un = ba + qa - inter;
            float iou = (un > 0.f) ? __fdiv_rn(inter, un) : 0.f;  // IEEE div
            if (iou > IOU_T) s_score[i] = NEG;
            else if (s > nb) { nb = s; ni = i; }
        }
        __syncthreads();                          // all suppression done (each thread owns its slots)
        block_argmax512(nb, ni, s_rs, s_ri, &sh_bs, &sh_bi, tid);
        bs = sh_bs; biG = sh_bi;
    }

    // fill unused slots
    for (int kk = k + tid; kk < K_; kk += NTH) {
        g_ks[out_base + kk] = NEG;
        ((float4*)g_kb)[out_base + kk] = make_float4(0.f, 0.f, 0.f, 0.f);
    }
}

// ---------------------------------------------------------------------------
// Kernel 2: per-batch cross-class top-K_. grid = B_, block = 256.
// Output layout (f32): boxes [B,K,4] | scores [B,K] | cls [B,K] | valid [B]
// ---------------------------------------------------------------------------
__global__ __launch_bounds__(256) void topk_kernel(float* __restrict__ out)
{
    __shared__ float s_s[C_ * K_];
    __shared__ float s_rs[8];
    __shared__ int   s_ri[8];
    __shared__ float sh_s[K_];
    __shared__ int   sh_i[K_];

    const int b    = blockIdx.x;
    const int tid  = threadIdx.x;
    const int lane = tid & 31;

    for (int j = tid; j < C_ * K_; j += 256) s_s[j] = g_ks[b * C_ * K_ + j];
    __syncthreads();

    for (int k = 0; k < K_; k++) {
        float best = -FLT_MAX; int bi = -1;
        for (int i = tid; i < C_ * K_; i += 256) {
            float s = s_s[i];
            if (s > best) { best = s; bi = i; }
        }
        #pragma unroll
        for (int off = 16; off; off >>= 1) {
            float s2 = __shfl_down_sync(0xffffffffu, best, off);
            int   i2 = __shfl_down_sync(0xffffffffu, bi, off);
            if (s2 > best || (s2 == best && (unsigned)i2 < (unsigned)bi)) { best = s2; bi = i2; }
        }
        if (lane == 0) { s_rs[tid >> 5] = best; s_ri[tid >> 5] = bi; }
        __syncthreads();
        if (tid < 32) {
            best = (tid < 8) ? s_rs[tid] : -FLT_MAX;
            bi   = (tid < 8) ? s_ri[tid] : -1;
            #pragma unroll
            for (int off = 4; off; off >>= 1) {
                float s2 = __shfl_down_sync(0xffffffffu, best, off);
                int   i2 = __shfl_down_sync(0xffffffffu, bi, off);
                if (s2 > best || (s2 == best && (unsigned)i2 < (unsigned)bi)) { best = s2; bi = i2; }
            }
            if (tid == 0) {
                sh_s[k] = best; sh_i[k] = bi;
                s_s[bi] = -FLT_MAX;               // never re-picked
            }
        }
        __syncthreads();
    }

    const int OB_scores = B_ * K_ * 4;
    const int OB_cls    = OB_scores + B_ * K_;
    const int OB_valid  = OB_cls + B_ * K_;

    if (tid < K_) {
        float s   = sh_s[tid];
        int   idx = sh_i[tid];
        bool  valid = s > SCORE_T;
        float4 bx = make_float4(0.f, 0.f, 0.f, 0.f);
        if (valid) {
            bx = ((float4*)g_kb)[b * C_ * K_ + idx];
            bx.x = fminf(fmaxf(bx.x, 0.f), 1.f);
            bx.y = fminf(fmaxf(bx.y, 0.f), 1.f);
            bx.z = fminf(fmaxf(bx.z, 0.f), 1.f);
            bx.w = fminf(fmaxf(bx.w, 0.f), 1.f);
        }
        int o = b * K_ + tid;
        ((float4*)out)[o]  = bx;
        out[OB_scores + o] = valid ? s : 0.f;
        out[OB_cls + o]    = valid ? (float)(idx / K_) : 0.f;
    }
    if (tid < 32) {
        bool v = (tid < K_) && (sh_s[tid] > SCORE_T);
        unsigned m = __ballot_sync(0xffffffffu, v);
        if (tid == 0) out[OB_valid + b] = (float)__popc(m);
    }
}

// ---------------------------------------------------------------------------
extern "C" void kernel_launch(void* const* d_in, const int* in_sizes, int n_in,
                              void* d_out, int out_size)
{
    const float* bbox0 = (const float*)d_in[0];
    const float* conf0 = (const float*)d_in[1];
    const float* cls0  = (const float*)d_in[2];
    const float* bbox1 = (const float*)d_in[3];
    const float* conf1 = (const float*)d_in[4];
    const float* cls1  = (const float*)d_in[5];
    const float* bbox2 = (const float*)d_in[6];
    const float* conf2 = (const float*)d_in[7];
    const float* cls2  = (const float*)d_in[8];

    const int NT = (N_ + 31) / 32;
    score_kernel<<<B_ * NT, 256>>>(conf0, cls0, conf1, cls1, conf2, cls2);

    const int smem_bytes = MAXC * (sizeof(float4) + sizeof(float)); // 71680
    cudaFuncSetAttribute(nms_kernel, cudaFuncAttributeMaxDynamicSharedMemorySize, smem_bytes);
    nms_kernel<<<B_ * C_, NTH, smem_bytes>>>(bbox0, bbox1, bbox2);

    topk_kernel<<<B_, 256>>>((float*)d_out);
}

// round 3
// speedup vs baseline: 6.3705x; 4.4279x over previous
#include <cuda_runtime.h>
#include <float.h>

#define B_       16
#define C_       80
#define N_       25200
#define N0_      19200
#define N1_      4800
#define N2_      1200
#define K_       25
#define NEG      (-1e30f)
#define SCORE_T  0.55f
#define NTH2     256
#define NBUCK    1024
#define HB       768              // static high band: score > 0.55 + 768/1024*0.45 = 0.8875
#define CAP      320
#define SORTN    512
#define BSCALE   (NBUCK / (1.0f - SCORE_T))
#define TILE_A   64

// rn32(inter/un) > 0.5  <=>  inter > (0.5 + 2^-25) * un   (exact in double)
#define IOU_EDGE 0.500000029802322387695312500

__device__ float g_scores[B_ * C_ * N_];          // transposed scores
__device__ float g_kb[B_ * C_ * K_ * 4];
__device__ float g_ks[B_ * C_ * K_];

// ---------------------------------------------------------------------------
// Kernel 0: score transpose.  score[b][c][n] = conf[b][n] * cls[b][n][c]
// 64-anchor tiles, float4 cls loads, conflict-free smem transpose.
// ---------------------------------------------------------------------------
__global__ __launch_bounds__(256) void score_kernel(
    const float* __restrict__ conf0, const float* __restrict__ cls0,
    const float* __restrict__ conf1, const float* __restrict__ cls1,
    const float* __restrict__ conf2, const float* __restrict__ cls2)
{
    __shared__ float s_tile[TILE_A][81];
    __shared__ float s_conf[TILE_A];

    const int NT   = (N_ + TILE_A - 1) / TILE_A;     // 394
    const int b    = blockIdx.x / NT;
    const int t    = blockIdx.x - b * NT;
    const int n0   = t * TILE_A;
    const int tid  = threadIdx.x;
    const int lane = tid & 31;
    const int w    = tid >> 5;
    const int va   = min(TILE_A, N_ - n0);

    const float *cf, *cl;
    int loc_base;
    if (n0 < N0_)             { cf = conf0; cl = cls0; loc_base = b * N0_ + n0; }
    else if (n0 < N0_ + N1_)  { cf = conf1; cl = cls1; loc_base = b * N1_ + (n0 - N0_); }
    else                      { cf = conf2; cl = cls2; loc_base = b * N2_ + (n0 - N0_ - N1_); }

    for (int v = tid; v < TILE_A * (C_ / 4); v += 256) {   // 64 * 20
        int a = v / 20, q = v - a * 20;
        if (a < va) {
            float4 t4 = ((const float4*)(cl + (size_t)(loc_base + a) * C_))[q];
            s_tile[a][q * 4 + 0] = t4.x;
            s_tile[a][q * 4 + 1] = t4.y;
            s_tile[a][q * 4 + 2] = t4.z;
            s_tile[a][q * 4 + 3] = t4.w;
        }
    }
    if (tid < TILE_A && tid < va) s_conf[tid] = cf[loc_base + tid];
    __syncthreads();

    #pragma unroll
    for (int cc = 0; cc < 10; cc++) {
        int c = w * 10 + cc;
        #pragma unroll
        for (int h = 0; h < 2; h++) {
            int a = h * 32 + lane;
            if (a < va)
                g_scores[(size_t)(b * C_ + c) * N_ + n0 + a] = s_conf[a] * s_tile[a][c];
        }
    }
}

// ---------------------------------------------------------------------------
// Kernel 1: per-(batch,class) NMS via histogram + sorted greedy walk.
// grid = B_*C_, block = NTH2. Static smem ~15 KB -> high occupancy.
// ---------------------------------------------------------------------------
__global__ __launch_bounds__(NTH2) void nms_kernel(
    const float* __restrict__ bbox0,
    const float* __restrict__ bbox1,
    const float* __restrict__ bbox2)
{
    __shared__ int                hist[NBUCK];
    __shared__ float4             c_box[CAP];
    __shared__ unsigned long long keys[SORTN];
    __shared__ int                sh_cnt;
    __shared__ int                sh_nk;
    __shared__ int                sh_lo;
    __shared__ int                sh_red[16];

    const int tid = threadIdx.x;
    const int b   = blockIdx.x / C_;
    const int c   = blockIdx.x - b * C_;
    const float4* sc_row4 = (const float4*)(g_scores + (size_t)(b * C_ + c) * N_);
    const int out_base = blockIdx.x * K_;

    for (int i = tid; i < NBUCK; i += NTH2) hist[i] = 0;
    if (tid == 0) { sh_cnt = 0; sh_nk = 0; }
    __syncthreads();

    // ---- Pass A: histogram + top-band candidate append (one streaming read)
    for (int i = tid; i < N_ / 4; i += NTH2) {
        float4 v = sc_row4[i];
        #pragma unroll
        for (int e = 0; e < 4; e++) {
            float sc = (e == 0) ? v.x : (e == 1) ? v.y : (e == 2) ? v.z : v.w;
            if (sc > SCORE_T) {
                int bkt = min((int)((sc - SCORE_T) * BSCALE), NBUCK - 1);
                atomicAdd(&hist[bkt], 1);
                if (bkt >= HB) {
                    int pos = atomicAdd(&sh_cnt, 1);
                    if (pos < CAP) {
                        int n = i * 4 + e;
                        const float* bb; int loc;
                        if (n < N0_)            { bb = bbox0; loc = b * N0_ + n; }
                        else if (n < N0_ + N1_) { bb = bbox1; loc = b * N1_ + (n - N0_); }
                        else                    { bb = bbox2; loc = b * N2_ + (n - N0_ - N1_); }
                        float4 t = ((const float4*)bb)[loc];
                        t.x = fmaxf(t.x, 0.f); t.y = fmaxf(t.y, 0.f);
                        t.z = fmaxf(t.z, 0.f); t.w = fmaxf(t.w, 0.f);
                        c_box[pos] = t;
                        keys[pos] = ((unsigned long long)__float_as_uint(sc) << 32)
                                  | ((unsigned long long)((~n) & 0x7FFF) << 9)
                                  | (unsigned long long)pos;
                    }
                }
            }
        }
    }
    __syncthreads();

    // ---- totals: total (>SCORE_T) and countHB (top band)
    int lt = 0, lhb = 0;
    for (int i = tid; i < NBUCK; i += NTH2) { int h = hist[i]; lt += h; if (i >= HB) lhb += h; }
    #pragma unroll
    for (int off = 16; off; off >>= 1) {
        lt  += __shfl_down_sync(0xffffffffu, lt, off);
        lhb += __shfl_down_sync(0xffffffffu, lhb, off);
    }
    if ((tid & 31) == 0) { sh_red[tid >> 5] = lt; sh_red[8 + (tid >> 5)] = lhb; }
    __syncthreads();
    int total = 0, countHB = 0;
    #pragma unroll
    for (int ww = 0; ww < NTH2 / 32; ww++) { total += sh_red[ww]; countHB += sh_red[8 + ww]; }

    // ---- chunked sorted greedy NMS
    bool first = true;
    bool hb_ok = (countHB <= CAP);
    bool suffix_done = false;
    int  hi = NBUCK, processed = 0;

    // kept boxes: lane l of warp 0 holds kept[l] (canonical corners + area)
    float ky1 = 0.f, kx1 = 0.f, ky2 = 0.f, kx2 = 0.f, karea = 0.f;

    while (processed < total && hi > 0) {
        if (sh_nk >= K_) break;
        int cnt, lo;

        if (first && hb_ok) {
            cnt = countHB; lo = HB;
        } else {
            if (!suffix_done) {
                if (tid == 0)
                    for (int q = NBUCK - 2; q >= 0; q--) hist[q] += hist[q + 1];
                suffix_done = true;
                __syncthreads();
            }
            if (tid == 0) {
                int l = hi - 1;
                while (l > 0 && hist[l - 1] - processed <= CAP) l--;
                sh_lo = l;
                sh_cnt = 0;
            }
            __syncthreads();
            lo = sh_lo;
            // rescan band [lo, hi)  (row is L2-hot)
            for (int i = tid; i < N_ / 4; i += NTH2) {
                float4 v = sc_row4[i];
                #pragma unroll
                for (int e = 0; e < 4; e++) {
                    float sc = (e == 0) ? v.x : (e == 1) ? v.y : (e == 2) ? v.z : v.w;
                    if (sc > SCORE_T) {
                        int bkt = min((int)((sc - SCORE_T) * BSCALE), NBUCK - 1);
                        if (bkt >= lo && bkt < hi) {
                            int pos = atomicAdd(&sh_cnt, 1);
                            if (pos < CAP) {
                                int n = i * 4 + e;
                                const float* bb; int loc;
                                if (n < N0_)            { bb = bbox0; loc = b * N0_ + n; }
                                else if (n < N0_ + N1_) { bb = bbox1; loc = b * N1_ + (n - N0_); }
                                else                    { bb = bbox2; loc = b * N2_ + (n - N0_ - N1_); }
                                float4 t = ((const float4*)bb)[loc];
                                t.x = fmaxf(t.x, 0.f); t.y = fmaxf(t.y, 0.f);
                                t.z = fmaxf(t.z, 0.f); t.w = fmaxf(t.w, 0.f);
                                c_box[pos] = t;
                                keys[pos] = ((unsigned long long)__float_as_uint(sc) << 32)
                                          | ((unsigned long long)((~n) & 0x7FFF) << 9)
                                          | (unsigned long long)pos;
                            }
                        }
                    }
                }
            }
            __syncthreads();
            cnt = min(sh_cnt, CAP);
        }
        first = false;

        if (cnt > 0) {
            // pad to pow2 and bitonic sort descending (score desc, index asc)
            int nsort = 32;
            while (nsort < cnt) nsort <<= 1;
            for (int j = cnt + tid; j < nsort; j += NTH2) keys[j] = 0ull;
            __syncthreads();
            for (int k2 = 2; k2 <= nsort; k2 <<= 1) {
                for (int j = k2 >> 1; j > 0; j >>= 1) {
                    for (int i = tid; i < nsort; i += NTH2) {
                        int p = i ^ j;
                        if (p > i) {
                            unsigned long long a = keys[i], q = keys[p];
                            bool dir = ((i & k2) == 0);
                            if ((q > a) == dir) { keys[i] = q; keys[p] = a; }
                        }
                    }
                    __syncthreads();
                }
            }

            // greedy walk: warp 0 only
            if (tid < 32) {
                const int lane = tid;
                int nk = sh_nk;
                for (int j = 0; j < cnt && nk < K_; j++) {
                    unsigned long long kk = keys[j];
                    int   pos = (int)(kk & 511ull);
                    float sc  = __uint_as_float((unsigned)(kk >> 32));
                    float4 bx = c_box[pos];
                    float y1 = fminf(bx.x, bx.z), y2 = fmaxf(bx.x, bx.z);
                    float x1 = fminf(bx.y, bx.w), x2 = fmaxf(bx.y, bx.w);
                    float ar = (y2 - y1) * (x2 - x1);
                    bool sup = false;
                    if (lane < nk) {
                        float ih = fmaxf(fminf(y2, ky2) - fmaxf(y1, ky1), 0.f);
                        float iw = fmaxf(fminf(x2, kx2) - fmaxf(x1, kx1), 0.f);
                        float inter = ih * iw;
                        float un = ar + karea - inter;
                        sup = (un > 0.f) && ((double)inter > IOU_EDGE * (double)un);
                    }
                    if (!__any_sync(0xffffffffu, sup)) {
                        if (lane == nk) { ky1 = y1; kx1 = x1; ky2 = y2; kx2 = x2; karea = ar; }
                        if (lane == 0) {
                            g_ks[out_base + nk] = sc;
                            ((float4*)g_kb)[out_base + nk] = bx;
                        }
                        nk++;
                    }
                }
                if (lane == 0) sh_nk = nk;
            }
        }
        processed += cnt;
        hi = lo;
        __syncthreads();
    }

    __syncthreads();
    int nkf = sh_nk;
    for (int kk2 = nkf + tid; kk2 < K_; kk2 += NTH2) {
        g_ks[out_base + kk2] = NEG;
        ((float4*)g_kb)[out_base + kk2] = make_float4(0.f, 0.f, 0.f, 0.f);
    }
}

// ---------------------------------------------------------------------------
// Kernel 2: per-batch cross-class top-K_. grid = B_, block = 256.
// Output (f32): boxes [B,K,4] | scores [B,K] | cls [B,K] | valid [B]
// ---------------------------------------------------------------------------
__global__ __launch_bounds__(256) void topk_kernel(float* __restrict__ out)
{
    __shared__ float s_s[C_ * K_];
    __shared__ float s_rs[8];
    __shared__ int   s_ri[8];
    __shared__ float sh_s[K_];
    __shared__ int   sh_i[K_];

    const int b    = blockIdx.x;
    const int tid  = threadIdx.x;
    const int lane = tid & 31;

    for (int j = tid; j < C_ * K_; j += 256) s_s[j] = g_ks[b * C_ * K_ + j];
    __syncthreads();

    for (int k = 0; k < K_; k++) {
        float best = -FLT_MAX; int bi = -1;
        for (int i = tid; i < C_ * K_; i += 256) {
            float s = s_s[i];
            if (s > best) { best = s; bi = i; }
        }
        #pragma unroll
        for (int off = 16; off; off >>= 1) {
            float s2 = __shfl_down_sync(0xffffffffu, best, off);
            int   i2 = __shfl_down_sync(0xffffffffu, bi, off);
            if (s2 > best || (s2 == best && (unsigned)i2 < (unsigned)bi)) { best = s2; bi = i2; }
        }
        if (lane == 0) { s_rs[tid >> 5] = best; s_ri[tid >> 5] = bi; }
        __syncthreads();
        if (tid < 32) {
            best = (tid < 8) ? s_rs[tid] : -FLT_MAX;
            bi   = (tid < 8) ? s_ri[tid] : -1;
            #pragma unroll
            for (int off = 4; off; off >>= 1) {
                float s2 = __shfl_down_sync(0xffffffffu, best, off);
                int   i2 = __shfl_down_sync(0xffffffffu, bi, off);
                if (s2 > best || (s2 == best && (unsigned)i2 < (unsigned)bi)) { best = s2; bi = i2; }
            }
            if (tid == 0) {
                sh_s[k] = best; sh_i[k] = bi;
                s_s[bi] = -FLT_MAX;
            }
        }
        __syncthreads();
    }

    const int OB_scores = B_ * K_ * 4;
    const int OB_cls    = OB_scores + B_ * K_;
    const int OB_valid  = OB_cls + B_ * K_;

    if (tid < K_) {
        float s   = sh_s[tid];
        int   idx = sh_i[tid];
        bool  valid = s > SCORE_T;
        float4 bx = make_float4(0.f, 0.f, 0.f, 0.f);
        if (valid) {
            bx = ((float4*)g_kb)[b * C_ * K_ + idx];
            bx.x = fminf(fmaxf(bx.x, 0.f), 1.f);
            bx.y = fminf(fmaxf(bx.y, 0.f), 1.f);
            bx.z = fminf(fmaxf(bx.z, 0.f), 1.f);
            bx.w = fminf(fmaxf(bx.w, 0.f), 1.f);
        }
        int o = b * K_ + tid;
        ((float4*)out)[o]  = bx;
        out[OB_scores + o] = valid ? s : 0.f;
        out[OB_cls + o]    = valid ? (float)(idx / K_) : 0.f;
    }
    if (tid < 32) {
        bool v = (tid < K_) && (sh_s[tid] > SCORE_T);
        unsigned m = __ballot_sync(0xffffffffu, v);
        if (tid == 0) out[OB_valid + b] = (float)__popc(m);
    }
}

// ---------------------------------------------------------------------------
extern "C" void kernel_launch(void* const* d_in, const int* in_sizes, int n_in,
                              void* d_out, int out_size)
{
    const float* bbox0 = (const float*)d_in[0];
    const float* conf0 = (const float*)d_in[1];
    const float* cls0  = (const float*)d_in[2];
    const float* bbox1 = (const float*)d_in[3];
    const float* conf1 = (const float*)d_in[4];
    const float* cls1  = (const float*)d_in[5];
    const float* bbox2 = (const float*)d_in[6];
    const float* conf2 = (const float*)d_in[7];
    const float* cls2  = (const float*)d_in[8];

    const int NT = (N_ + TILE_A - 1) / TILE_A;
    score_kernel<<<B_ * NT, 256>>>(conf0, cls0, conf1, cls1, conf2, cls2);
    nms_kernel<<<B_ * C_, NTH2>>>(bbox0, bbox1, bbox2);
    topk_kernel<<<B_, 256>>>((float*)d_out);
}